// round 1
// baseline (speedup 1.0000x reference)
#include <cuda_runtime.h>
#include <cuda_bf16.h>

// Problem constants
// x: (32, 56, 56, 384), WS=7, NH=12, HD=32, C=384
// tokens (window-major) = 32 * 64 * 49 = 100352
#define B_    32
#define HW_   56
#define C_    384
#define NH_   12
#define HD_   32
#define WS_   7
#define NWIN_ 64          // 8*8 windows per image
#define P_    49          // tokens per window
#define TOK_  100352      // B_*NWIN_*P_
#define BW_   2048        // B_*NWIN_
#define QKVN_ 1152        // 3*C_

// Scratch (device globals — no allocation allowed)
__device__ float g_q[BW_ * NH_ * P_ * HD_];     // [w*12+h][p][d]
__device__ float g_k[BW_ * NH_ * P_ * HD_];
__device__ float g_v[BW_ * NH_ * P_ * HD_];
__device__ float g_attn[TOK_ * C_];             // token-major attention output

// token index -> offset into x / out (both are [b,56,56,384])
__device__ __forceinline__ int token_to_xoff(int t) {
    int b  = t / 3136;          // 64*49
    int r  = t - b * 3136;
    int w  = r / 49;
    int pp = r - w * 49;
    int wi = w >> 3, wj = w & 7;
    int pi = pp / 7, pj = pp - pi * 7;
    return ((b * 56 + wi * 7 + pi) * 56 + (wj * 7 + pj)) * 384;
}

// ---------------------------------------------------------------------------
// GEMM config: 128x64 tile, BK=16, 256 threads, 8x4 per thread, double buffer
// ---------------------------------------------------------------------------
#define BM 128
#define BN 64
#define BK 16
#define BMP 132   // padded lead dim for As (keeps 16B alignment, breaks bank conflicts)

// Kernel 1: QKV = gather(x) @ w_qkv + b_qkv, scatter into g_q/g_k/g_v
__global__ __launch_bounds__(256) void qkv_kernel(const float* __restrict__ x,
                                                  const float* __restrict__ wqkv,
                                                  const float* __restrict__ bqkv) {
    __shared__ float As[2][BK][BMP];
    __shared__ float Bs[2][BK][BN];

    const int tid = threadIdx.x;
    const int m0 = blockIdx.x * BM;
    const int n0 = blockIdx.y * BN;

    // A loader: each thread loads 2 float4 (rows arow, arow+64), cols acol..acol+3
    const int arow = tid >> 2;               // 0..63
    const int acol = (tid & 3) << 2;         // 0,4,8,12
    const float* aptr0 = x + token_to_xoff(m0 + arow) + acol;
    const float* aptr1 = x + token_to_xoff(m0 + arow + 64) + acol;

    // B loader: one float4 per thread
    const int brow = tid >> 4;               // 0..15
    const int bcol = (tid & 15) << 2;        // 0..60
    const float* bptr = wqkv + brow * QKVN_ + n0 + bcol;

    const int ty = tid >> 4;                 // 0..15  (m dir)
    const int tx = tid & 15;                 // 0..15  (n dir)

    float acc[8][4];
#pragma unroll
    for (int i = 0; i < 8; i++)
#pragma unroll
        for (int j = 0; j < 4; j++) acc[i][j] = 0.f;

    // preload tile 0
    float4 ra0 = *(const float4*)(aptr0);
    float4 ra1 = *(const float4*)(aptr1);
    float4 rb  = *(const float4*)(bptr);
    As[0][acol + 0][arow] = ra0.x; As[0][acol + 1][arow] = ra0.y;
    As[0][acol + 2][arow] = ra0.z; As[0][acol + 3][arow] = ra0.w;
    As[0][acol + 0][arow + 64] = ra1.x; As[0][acol + 1][arow + 64] = ra1.y;
    As[0][acol + 2][arow + 64] = ra1.z; As[0][acol + 3][arow + 64] = ra1.w;
    *(float4*)&Bs[0][brow][bcol] = rb;
    __syncthreads();

    const int NT = C_ / BK;   // 24
    for (int kt = 0; kt < NT; kt++) {
        const int cur = kt & 1;
        if (kt + 1 < NT) {
            const int koff = (kt + 1) * BK;
            ra0 = *(const float4*)(aptr0 + koff);
            ra1 = *(const float4*)(aptr1 + koff);
            rb  = *(const float4*)(bptr + koff * QKVN_);
        }
#pragma unroll
        for (int kk = 0; kk < BK; kk++) {
            float4 a0 = *(const float4*)&As[cur][kk][ty * 8];
            float4 a1 = *(const float4*)&As[cur][kk][ty * 8 + 4];
            float4 b  = *(const float4*)&Bs[cur][kk][tx * 4];
            float av[8] = {a0.x, a0.y, a0.z, a0.w, a1.x, a1.y, a1.z, a1.w};
            float bv[4] = {b.x, b.y, b.z, b.w};
#pragma unroll
            for (int i = 0; i < 8; i++)
#pragma unroll
                for (int j = 0; j < 4; j++) acc[i][j] = fmaf(av[i], bv[j], acc[i][j]);
        }
        if (kt + 1 < NT) {
            const int nxt = cur ^ 1;
            As[nxt][acol + 0][arow] = ra0.x; As[nxt][acol + 1][arow] = ra0.y;
            As[nxt][acol + 2][arow] = ra0.z; As[nxt][acol + 3][arow] = ra0.w;
            As[nxt][acol + 0][arow + 64] = ra1.x; As[nxt][acol + 1][arow + 64] = ra1.y;
            As[nxt][acol + 2][arow + 64] = ra1.z; As[nxt][acol + 3][arow + 64] = ra1.w;
            *(float4*)&Bs[nxt][brow][bcol] = rb;
            __syncthreads();
        }
    }

    // Epilogue: scatter into head-major q/k/v
#pragma unroll
    for (int i = 0; i < 8; i++) {
        const int m  = m0 + ty * 8 + i;
        const int w  = m / 49;
        const int pp = m - w * 49;
#pragma unroll
        for (int j = 0; j < 4; j++) {
            const int n = n0 + tx * 4 + j;
            float v = acc[i][j] + __ldg(&bqkv[n]);
            const int which = n / C_;
            const int nn    = n - which * C_;
            const int head  = nn >> 5;
            const int d     = nn & 31;
            float* dst = (which == 0) ? g_q : ((which == 1) ? g_k : g_v);
            dst[((w * NH_ + head) * P_ + pp) * HD_ + d] = v;
        }
    }
}

// ---------------------------------------------------------------------------
// Kernel 2: per (window, head) attention. 1 CTA = 1 (w,h). 256 threads.
// ---------------------------------------------------------------------------
__global__ __launch_bounds__(256) void attn_kernel(const float* __restrict__ rel_pos) {
    const int wh = blockIdx.x;            // w*12 + h
    const int h  = wh % NH_;
    const int w  = wh / NH_;
    const int tid = threadIdx.x;

    __shared__ float Qs[P_ * HD_];
    __shared__ float Ks[P_ * HD_];
    __shared__ float Vs[P_ * HD_];
    __shared__ float Ss[P_ * P_];
    __shared__ float Bb[13 * 13];

    const float4* qg = (const float4*)(g_q + wh * (P_ * HD_));
    const float4* kg = (const float4*)(g_k + wh * (P_ * HD_));
    const float4* vg = (const float4*)(g_v + wh * (P_ * HD_));
#pragma unroll
    for (int idx = tid; idx < (P_ * HD_) / 4; idx += 256) {
        ((float4*)Qs)[idx] = qg[idx];
        ((float4*)Ks)[idx] = kg[idx];
        ((float4*)Vs)[idx] = vg[idx];
    }
    if (tid < 169) Bb[tid] = rel_pos[h * 169 + tid];
    __syncthreads();

    const float scale = 0.17677669529663687f;  // 32^-0.5

    // S = scale * Q K^T + bias
    for (int e = tid; e < P_ * P_; e += 256) {
        const int i = e / 49;
        const int j = e - i * 49;
        const float4* qa = (const float4*)(Qs + i * HD_);
        const float4* kb = (const float4*)(Ks + j * HD_);
        float s = 0.f;
#pragma unroll
        for (int u = 0; u < HD_ / 4; u++) {
            float4 a = qa[u], b = kb[u];
            s = fmaf(a.x, b.x, s); s = fmaf(a.y, b.y, s);
            s = fmaf(a.z, b.z, s); s = fmaf(a.w, b.w, s);
        }
        const int di = i / 7 - j / 7 + 6;
        const int dj = (i % 7) - (j % 7) + 6;
        Ss[e] = fmaf(s, scale, Bb[di * 13 + dj]);
    }
    __syncthreads();

    // softmax over rows (warp per row)
    const int lane = tid & 31;
    const int warp = tid >> 5;
    for (int row = warp; row < P_; row += 8) {
        float* srow = Ss + row * 49;
        float v0 = srow[lane];                                   // lane < 32 < 49
        float v1 = (lane + 32 < 49) ? srow[lane + 32] : -1e30f;
        float m = fmaxf(v0, v1);
#pragma unroll
        for (int o = 16; o; o >>= 1) m = fmaxf(m, __shfl_xor_sync(~0u, m, o));
        float e0 = __expf(v0 - m);
        float e1 = (lane + 32 < 49) ? __expf(v1 - m) : 0.f;
        float sum = e0 + e1;
#pragma unroll
        for (int o = 16; o; o >>= 1) sum += __shfl_xor_sync(~0u, sum, o);
        float inv = 1.f / sum;
        srow[lane] = e0 * inv;
        if (lane + 32 < 49) srow[lane + 32] = e1 * inv;
    }
    __syncthreads();

    // O = P V, write token-major into g_attn
    for (int e = tid; e < P_ * HD_; e += 256) {
        const int i = e >> 5;
        const int d = e & 31;
        const float* prow = Ss + i * 49;
        const float* vcol = Vs + d;
        float o = 0.f;
#pragma unroll
        for (int j = 0; j < P_; j++) o = fmaf(prow[j], vcol[j * HD_], o);
        g_attn[(w * P_ + i) * C_ + h * HD_ + d] = o;
    }
}

// ---------------------------------------------------------------------------
// Kernel 3: out = g_attn @ w_out + b_out, scatter back to image layout
// ---------------------------------------------------------------------------
__global__ __launch_bounds__(256) void proj_kernel(const float* __restrict__ wout,
                                                   const float* __restrict__ bout,
                                                   float* __restrict__ out) {
    __shared__ float As[2][BK][BMP];
    __shared__ float Bs[2][BK][BN];

    const int tid = threadIdx.x;
    const int m0 = blockIdx.x * BM;
    const int n0 = blockIdx.y * BN;

    const int arow = tid >> 2;
    const int acol = (tid & 3) << 2;
    const float* aptr0 = g_attn + (m0 + arow) * C_ + acol;
    const float* aptr1 = g_attn + (m0 + arow + 64) * C_ + acol;

    const int brow = tid >> 4;
    const int bcol = (tid & 15) << 2;
    const float* bptr = wout + brow * C_ + n0 + bcol;

    const int ty = tid >> 4;
    const int tx = tid & 15;

    float acc[8][4];
#pragma unroll
    for (int i = 0; i < 8; i++)
#pragma unroll
        for (int j = 0; j < 4; j++) acc[i][j] = 0.f;

    float4 ra0 = *(const float4*)(aptr0);
    float4 ra1 = *(const float4*)(aptr1);
    float4 rb  = *(const float4*)(bptr);
    As[0][acol + 0][arow] = ra0.x; As[0][acol + 1][arow] = ra0.y;
    As[0][acol + 2][arow] = ra0.z; As[0][acol + 3][arow] = ra0.w;
    As[0][acol + 0][arow + 64] = ra1.x; As[0][acol + 1][arow + 64] = ra1.y;
    As[0][acol + 2][arow + 64] = ra1.z; As[0][acol + 3][arow + 64] = ra1.w;
    *(float4*)&Bs[0][brow][bcol] = rb;
    __syncthreads();

    const int NT = C_ / BK;  // 24
    for (int kt = 0; kt < NT; kt++) {
        const int cur = kt & 1;
        if (kt + 1 < NT) {
            const int koff = (kt + 1) * BK;
            ra0 = *(const float4*)(aptr0 + koff);
            ra1 = *(const float4*)(aptr1 + koff);
            rb  = *(const float4*)(bptr + koff * C_);
        }
#pragma unroll
        for (int kk = 0; kk < BK; kk++) {
            float4 a0 = *(const float4*)&As[cur][kk][ty * 8];
            float4 a1 = *(const float4*)&As[cur][kk][ty * 8 + 4];
            float4 b  = *(const float4*)&Bs[cur][kk][tx * 4];
            float av[8] = {a0.x, a0.y, a0.z, a0.w, a1.x, a1.y, a1.z, a1.w};
            float bv[4] = {b.x, b.y, b.z, b.w};
#pragma unroll
            for (int i = 0; i < 8; i++)
#pragma unroll
                for (int j = 0; j < 4; j++) acc[i][j] = fmaf(av[i], bv[j], acc[i][j]);
        }
        if (kt + 1 < NT) {
            const int nxt = cur ^ 1;
            As[nxt][acol + 0][arow] = ra0.x; As[nxt][acol + 1][arow] = ra0.y;
            As[nxt][acol + 2][arow] = ra0.z; As[nxt][acol + 3][arow] = ra0.w;
            As[nxt][acol + 0][arow + 64] = ra1.x; As[nxt][acol + 1][arow + 64] = ra1.y;
            As[nxt][acol + 2][arow + 64] = ra1.z; As[nxt][acol + 3][arow + 64] = ra1.w;
            *(float4*)&Bs[nxt][brow][bcol] = rb;
            __syncthreads();
        }
    }

#pragma unroll
    for (int i = 0; i < 8; i++) {
        const int m = m0 + ty * 8 + i;
        const int xoff = token_to_xoff(m);
#pragma unroll
        for (int j = 0; j < 4; j++) {
            const int n = n0 + tx * 4 + j;
            out[xoff + n] = acc[i][j] + __ldg(&bout[n]);
        }
    }
}

// ---------------------------------------------------------------------------
extern "C" void kernel_launch(void* const* d_in, const int* in_sizes, int n_in,
                              void* d_out, int out_size) {
    (void)in_sizes; (void)n_in; (void)out_size;
    const float* x      = (const float*)d_in[0];
    const float* w_qkv  = (const float*)d_in[1];
    const float* b_qkv  = (const float*)d_in[2];
    const float* relpos = (const float*)d_in[3];
    const float* w_out  = (const float*)d_in[4];
    const float* b_out  = (const float*)d_in[5];
    float* out = (float*)d_out;

    dim3 g1(TOK_ / BM, QKVN_ / BN);   // 784 x 18
    qkv_kernel<<<g1, 256>>>(x, w_qkv, b_qkv);

    attn_kernel<<<BW_ * NH_, 256>>>(relpos);   // 24576 CTAs

    dim3 g3(TOK_ / BM, C_ / BN);      // 784 x 6
    proj_kernel<<<g3, 256>>>(w_out, b_out, out);
}

// round 3
// speedup vs baseline: 1.0284x; 1.0284x over previous
#include <cuda_runtime.h>
#include <cuda_bf16.h>
#include <stdint.h>

#define C_    384
#define NH_   12
#define HD_   32
#define P_    49
#define BW_   2048
#define TOK_  100352
#define QKVN_ 1152

// Scratch (device globals — no allocation allowed)
__device__ float g_q[BW_ * NH_ * P_ * HD_];
__device__ float g_k[BW_ * NH_ * P_ * HD_];
__device__ float g_v[BW_ * NH_ * P_ * HD_];
__device__ float g_attn[TOK_ * C_];
__device__ __nv_bfloat16 g_wqkvT_h[QKVN_ * C_];
__device__ __nv_bfloat16 g_wqkvT_l[QKVN_ * C_];
__device__ __nv_bfloat16 g_woutT_h[C_ * C_];
__device__ __nv_bfloat16 g_woutT_l[C_ * C_];

__device__ __forceinline__ int token_to_xoff(int t) {
    int b  = t / 3136;
    int r  = t - b * 3136;
    int w  = r / 49;
    int pp = r - w * 49;
    int wi = w >> 3, wj = w & 7;
    int pi = pp / 7, pj = pp - pi * 7;
    return ((b * 56 + wi * 7 + pi) * 56 + (wj * 7 + pj)) * 384;
}

__global__ void prep_weights(const float* __restrict__ wqkv,
                             const float* __restrict__ wout) {
    int idx = blockIdx.x * 256 + threadIdx.x;
    if (idx < QKVN_ * C_) {
        int n = idx / C_;
        int k = idx - n * C_;
        float v = wqkv[k * QKVN_ + n];
        __nv_bfloat16 h = __float2bfloat16(v);
        g_wqkvT_h[idx] = h;
        g_wqkvT_l[idx] = __float2bfloat16(v - __bfloat162float(h));
    } else {
        int j = idx - QKVN_ * C_;
        if (j < C_ * C_) {
            int n = j / C_;
            int k = j - n * C_;
            float v = wout[k * C_ + n];
            __nv_bfloat16 h = __float2bfloat16(v);
            g_woutT_h[j] = h;
            g_woutT_l[j] = __float2bfloat16(v - __bfloat162float(h));
        }
    }
}

__device__ __forceinline__ void ldm4(uint32_t* r, const __nv_bfloat16* p) {
    uint32_t addr = (uint32_t)__cvta_generic_to_shared(p);
    asm volatile("ldmatrix.sync.aligned.m8n8.x4.shared.b16 {%0,%1,%2,%3}, [%4];"
                 : "=r"(r[0]), "=r"(r[1]), "=r"(r[2]), "=r"(r[3]) : "r"(addr));
}

__device__ __forceinline__ void mma16816(float* c, const uint32_t* a, const uint32_t* b) {
    asm volatile("mma.sync.aligned.m16n8k16.row.col.f32.bf16.bf16.f32 "
                 "{%0,%1,%2,%3}, {%4,%5,%6,%7}, {%8,%9}, {%0,%1,%2,%3};"
                 : "+f"(c[0]), "+f"(c[1]), "+f"(c[2]), "+f"(c[3])
                 : "r"(a[0]), "r"(a[1]), "r"(a[2]), "r"(a[3]), "r"(b[0]), "r"(b[1]));
}

__device__ __forceinline__ void split_store8(float4 a, float4 b,
                                             __nv_bfloat16* dh, __nv_bfloat16* dl) {
    float f[8];
    f[0] = a.x; f[1] = a.y; f[2] = a.z; f[3] = a.w;
    f[4] = b.x; f[5] = b.y; f[6] = b.z; f[7] = b.w;
    uint32_t hw[4];
    uint32_t lw[4];
#pragma unroll
    for (int i = 0; i < 4; i++) {
        __nv_bfloat16 h0 = __float2bfloat16(f[2 * i]);
        __nv_bfloat16 h1 = __float2bfloat16(f[2 * i + 1]);
        __nv_bfloat16 l0 = __float2bfloat16(f[2 * i] - __bfloat162float(h0));
        __nv_bfloat16 l1 = __float2bfloat16(f[2 * i + 1] - __bfloat162float(h1));
        hw[i] = (uint32_t)__bfloat16_as_ushort(h0) | ((uint32_t)__bfloat16_as_ushort(h1) << 16);
        lw[i] = (uint32_t)__bfloat16_as_ushort(l0) | ((uint32_t)__bfloat16_as_ushort(l1) << 16);
    }
    uint32_t* ph = (uint32_t*)dh;
    uint32_t* pl = (uint32_t*)dl;
#pragma unroll
    for (int i = 0; i < 4; i++) {
        ph[i] = hw[i];
        pl[i] = lw[i];
    }
}

__device__ __forceinline__ void scatter_qkv(int w, int pp, int n, float v) {
    int which = n / C_;
    int nn = n - which * C_;
    int head = nn >> 5;
    int d = nn & 31;
    float* dst = (which == 0) ? g_q : ((which == 1) ? g_k : g_v);
    dst[((w * NH_ + head) * P_ + pp) * HD_ + d] = v;
}

#define BM 128
#define BN 64
#define BK 16
#define BKP 24

// ---------------------------------------------------------------------------
// Kernel 1: QKV GEMM (gather x, scatter q/k/v)
// ---------------------------------------------------------------------------
__global__ __launch_bounds__(256) void qkv_mma(const float* __restrict__ x,
                                               const float* __restrict__ bias) {
    __shared__ __nv_bfloat16 AsH[2][BM][BKP];
    __shared__ __nv_bfloat16 AsL[2][BM][BKP];
    __shared__ __nv_bfloat16 BsH[2][BN][BKP];
    __shared__ __nv_bfloat16 BsL[2][BN][BKP];

    const int tid = threadIdx.x;
    const int m0 = blockIdx.x * BM;
    const int n0 = blockIdx.y * BN;

    const int arow  = tid >> 1;
    const int akoff = (tid & 1) * 8;
    const float* aptr = x + token_to_xoff(m0 + arow) + akoff;

    const int bhalf = tid >> 7;
    const int t2    = tid & 127;
    const int brow  = t2 >> 1;
    const int bkoff = (t2 & 1) * 8;
    const __nv_bfloat16* bptr =
        (bhalf ? g_wqkvT_l : g_wqkvT_h) + (n0 + brow) * C_ + bkoff;

    const int warp = tid >> 5;
    const int lane = tid & 31;
    const int wm = (warp >> 1) * 32;
    const int wn = (warp & 1) * 32;
    const int grp = lane >> 3;
    const int lr = lane & 7;
    const int a_r = (grp & 1) * 8 + lr;
    const int a_k = (grp >> 1) * 8;
    const int b_r = (grp >> 1) * 8 + lr;
    const int b_k = (grp & 1) * 8;

    float acc[2][4][4];
#pragma unroll
    for (int i = 0; i < 2; i++) {
#pragma unroll
        for (int j = 0; j < 4; j++) {
#pragma unroll
            for (int e = 0; e < 4; e++) acc[i][j][e] = 0.f;
        }
    }

    float4 fa0 = *(const float4*)(aptr);
    float4 fa1 = *(const float4*)(aptr + 4);
    uint32_t rbw[4];
    rbw[0] = ((const uint32_t*)bptr)[0];
    rbw[1] = ((const uint32_t*)bptr)[1];
    rbw[2] = ((const uint32_t*)bptr)[2];
    rbw[3] = ((const uint32_t*)bptr)[3];

    split_store8(fa0, fa1, &AsH[0][arow][akoff], &AsL[0][arow][akoff]);
    {
        uint32_t* bd = (uint32_t*)(bhalf ? &BsL[0][brow][bkoff] : &BsH[0][brow][bkoff]);
        bd[0] = rbw[0]; bd[1] = rbw[1]; bd[2] = rbw[2]; bd[3] = rbw[3];
    }
    __syncthreads();

    const int NT = C_ / BK;
    for (int kt = 0; kt < NT; kt++) {
        const int cur = kt & 1;
        if (kt + 1 < NT) {
            const int kg = (kt + 1) * BK;
            fa0 = *(const float4*)(aptr + kg);
            fa1 = *(const float4*)(aptr + kg + 4);
            rbw[0] = ((const uint32_t*)(bptr + kg))[0];
            rbw[1] = ((const uint32_t*)(bptr + kg))[1];
            rbw[2] = ((const uint32_t*)(bptr + kg))[2];
            rbw[3] = ((const uint32_t*)(bptr + kg))[3];
        }

        uint32_t ah[2][4];
        uint32_t al[2][4];
        uint32_t bh[4][2];
        uint32_t bl[4][2];
#pragma unroll
        for (int i = 0; i < 2; i++) {
            ldm4(ah[i], &AsH[cur][wm + i * 16 + a_r][a_k]);
            ldm4(al[i], &AsL[cur][wm + i * 16 + a_r][a_k]);
        }
#pragma unroll
        for (int q = 0; q < 2; q++) {
            uint32_t t[4];
            ldm4(t, &BsH[cur][wn + q * 16 + b_r][b_k]);
            bh[q * 2][0] = t[0]; bh[q * 2][1] = t[1];
            bh[q * 2 + 1][0] = t[2]; bh[q * 2 + 1][1] = t[3];
            ldm4(t, &BsL[cur][wn + q * 16 + b_r][b_k]);
            bl[q * 2][0] = t[0]; bl[q * 2][1] = t[1];
            bl[q * 2 + 1][0] = t[2]; bl[q * 2 + 1][1] = t[3];
        }

#pragma unroll
        for (int i = 0; i < 2; i++) {
#pragma unroll
            for (int j = 0; j < 4; j++) {
                mma16816(acc[i][j], ah[i], bh[j]);
                mma16816(acc[i][j], ah[i], bl[j]);
                mma16816(acc[i][j], al[i], bh[j]);
            }
        }

        if (kt + 1 < NT) {
            const int nxt = cur ^ 1;
            split_store8(fa0, fa1, &AsH[nxt][arow][akoff], &AsL[nxt][arow][akoff]);
            uint32_t* bd = (uint32_t*)(bhalf ? &BsL[nxt][brow][bkoff] : &BsH[nxt][brow][bkoff]);
            bd[0] = rbw[0]; bd[1] = rbw[1]; bd[2] = rbw[2]; bd[3] = rbw[3];
            __syncthreads();
        }
    }

    const int gid = lane >> 2;
    const int ctid = lane & 3;
#pragma unroll
    for (int i = 0; i < 2; i++) {
        const int r0 = m0 + wm + i * 16 + gid;
        const int r1 = r0 + 8;
        const int w0 = r0 / 49;
        const int p0 = r0 - w0 * 49;
        const int w1 = r1 / 49;
        const int p1 = r1 - w1 * 49;
#pragma unroll
        for (int j = 0; j < 4; j++) {
            const int n = n0 + wn + j * 8 + 2 * ctid;
            const float bz0 = __ldg(&bias[n]);
            const float bz1 = __ldg(&bias[n + 1]);
            scatter_qkv(w0, p0, n,     acc[i][j][0] + bz0);
            scatter_qkv(w0, p0, n + 1, acc[i][j][1] + bz1);
            scatter_qkv(w1, p1, n,     acc[i][j][2] + bz0);
            scatter_qkv(w1, p1, n + 1, acc[i][j][3] + bz1);
        }
    }
}

// ---------------------------------------------------------------------------
// Kernel 3: output projection GEMM (A = g_attn, scatter to image layout)
// ---------------------------------------------------------------------------
__global__ __launch_bounds__(256) void proj_mma(const float* __restrict__ bias,
                                                float* __restrict__ outp) {
    __shared__ __nv_bfloat16 AsH[2][BM][BKP];
    __shared__ __nv_bfloat16 AsL[2][BM][BKP];
    __shared__ __nv_bfloat16 BsH[2][BN][BKP];
    __shared__ __nv_bfloat16 BsL[2][BN][BKP];

    const int tid = threadIdx.x;
    const int m0 = blockIdx.x * BM;
    const int n0 = blockIdx.y * BN;

    const int arow  = tid >> 1;
    const int akoff = (tid & 1) * 8;
    const float* aptr = g_attn + (m0 + arow) * C_ + akoff;

    const int bhalf = tid >> 7;
    const int t2    = tid & 127;
    const int brow  = t2 >> 1;
    const int bkoff = (t2 & 1) * 8;
    const __nv_bfloat16* bptr =
        (bhalf ? g_woutT_l : g_woutT_h) + (n0 + brow) * C_ + bkoff;

    const int warp = tid >> 5;
    const int lane = tid & 31;
    const int wm = (warp >> 1) * 32;
    const int wn = (warp & 1) * 32;
    const int grp = lane >> 3;
    const int lr = lane & 7;
    const int a_r = (grp & 1) * 8 + lr;
    const int a_k = (grp >> 1) * 8;
    const int b_r = (grp >> 1) * 8 + lr;
    const int b_k = (grp & 1) * 8;

    float acc[2][4][4];
#pragma unroll
    for (int i = 0; i < 2; i++) {
#pragma unroll
        for (int j = 0; j < 4; j++) {
#pragma unroll
            for (int e = 0; e < 4; e++) acc[i][j][e] = 0.f;
        }
    }

    float4 fa0 = *(const float4*)(aptr);
    float4 fa1 = *(const float4*)(aptr + 4);
    uint32_t rbw[4];
    rbw[0] = ((const uint32_t*)bptr)[0];
    rbw[1] = ((const uint32_t*)bptr)[1];
    rbw[2] = ((const uint32_t*)bptr)[2];
    rbw[3] = ((const uint32_t*)bptr)[3];

    split_store8(fa0, fa1, &AsH[0][arow][akoff], &AsL[0][arow][akoff]);
    {
        uint32_t* bd = (uint32_t*)(bhalf ? &BsL[0][brow][bkoff] : &BsH[0][brow][bkoff]);
        bd[0] = rbw[0]; bd[1] = rbw[1]; bd[2] = rbw[2]; bd[3] = rbw[3];
    }
    __syncthreads();

    const int NT = C_ / BK;
    for (int kt = 0; kt < NT; kt++) {
        const int cur = kt & 1;
        if (kt + 1 < NT) {
            const int kg = (kt + 1) * BK;
            fa0 = *(const float4*)(aptr + kg);
            fa1 = *(const float4*)(aptr + kg + 4);
            rbw[0] = ((const uint32_t*)(bptr + kg))[0];
            rbw[1] = ((const uint32_t*)(bptr + kg))[1];
            rbw[2] = ((const uint32_t*)(bptr + kg))[2];
            rbw[3] = ((const uint32_t*)(bptr + kg))[3];
        }

        uint32_t ah[2][4];
        uint32_t al[2][4];
        uint32_t bh[4][2];
        uint32_t bl[4][2];
#pragma unroll
        for (int i = 0; i < 2; i++) {
            ldm4(ah[i], &AsH[cur][wm + i * 16 + a_r][a_k]);
            ldm4(al[i], &AsL[cur][wm + i * 16 + a_r][a_k]);
        }
#pragma unroll
        for (int q = 0; q < 2; q++) {
            uint32_t t[4];
            ldm4(t, &BsH[cur][wn + q * 16 + b_r][b_k]);
            bh[q * 2][0] = t[0]; bh[q * 2][1] = t[1];
            bh[q * 2 + 1][0] = t[2]; bh[q * 2 + 1][1] = t[3];
            ldm4(t, &BsL[cur][wn + q * 16 + b_r][b_k]);
            bl[q * 2][0] = t[0]; bl[q * 2][1] = t[1];
            bl[q * 2 + 1][0] = t[2]; bl[q * 2 + 1][1] = t[3];
        }

#pragma unroll
        for (int i = 0; i < 2; i++) {
#pragma unroll
            for (int j = 0; j < 4; j++) {
                mma16816(acc[i][j], ah[i], bh[j]);
                mma16816(acc[i][j], ah[i], bl[j]);
                mma16816(acc[i][j], al[i], bh[j]);
            }
        }

        if (kt + 1 < NT) {
            const int nxt = cur ^ 1;
            split_store8(fa0, fa1, &AsH[nxt][arow][akoff], &AsL[nxt][arow][akoff]);
            uint32_t* bd = (uint32_t*)(bhalf ? &BsL[nxt][brow][bkoff] : &BsH[nxt][brow][bkoff]);
            bd[0] = rbw[0]; bd[1] = rbw[1]; bd[2] = rbw[2]; bd[3] = rbw[3];
            __syncthreads();
        }
    }

    const int gid = lane >> 2;
    const int ctid = lane & 3;
#pragma unroll
    for (int i = 0; i < 2; i++) {
        const int r0 = m0 + wm + i * 16 + gid;
        const int r1 = r0 + 8;
        const int x0 = token_to_xoff(r0);
        const int x1 = token_to_xoff(r1);
#pragma unroll
        for (int j = 0; j < 4; j++) {
            const int n = n0 + wn + j * 8 + 2 * ctid;
            const float bz0 = __ldg(&bias[n]);
            const float bz1 = __ldg(&bias[n + 1]);
            outp[x0 + n]     = acc[i][j][0] + bz0;
            outp[x0 + n + 1] = acc[i][j][1] + bz1;
            outp[x1 + n]     = acc[i][j][2] + bz0;
            outp[x1 + n + 1] = acc[i][j][3] + bz1;
        }
    }
}

// ---------------------------------------------------------------------------
// Kernel 2: per (window, head) attention — proven in Round 1
// ---------------------------------------------------------------------------
__global__ __launch_bounds__(256) void attn_kernel(const float* __restrict__ rel_pos) {
    const int wh = blockIdx.x;
    const int h  = wh % NH_;
    const int w  = wh / NH_;
    const int tid = threadIdx.x;

    __shared__ float Qs[P_ * HD_];
    __shared__ float Ks[P_ * HD_];
    __shared__ float Vs[P_ * HD_];
    __shared__ float Ss[P_ * P_];
    __shared__ float Bb[13 * 13];

    const float4* qg = (const float4*)(g_q + wh * (P_ * HD_));
    const float4* kg = (const float4*)(g_k + wh * (P_ * HD_));
    const float4* vg = (const float4*)(g_v + wh * (P_ * HD_));
    for (int idx = tid; idx < (P_ * HD_) / 4; idx += 256) {
        ((float4*)Qs)[idx] = qg[idx];
        ((float4*)Ks)[idx] = kg[idx];
        ((float4*)Vs)[idx] = vg[idx];
    }
    if (tid < 169) Bb[tid] = rel_pos[h * 169 + tid];
    __syncthreads();

    const float scale = 0.17677669529663687f;

    for (int e = tid; e < P_ * P_; e += 256) {
        const int i = e / 49;
        const int j = e - i * 49;
        const float4* qa = (const float4*)(Qs + i * HD_);
        const float4* kb = (const float4*)(Ks + j * HD_);
        float s = 0.f;
#pragma unroll
        for (int u = 0; u < HD_ / 4; u++) {
            float4 a = qa[u];
            float4 b = kb[u];
            s = fmaf(a.x, b.x, s);
            s = fmaf(a.y, b.y, s);
            s = fmaf(a.z, b.z, s);
            s = fmaf(a.w, b.w, s);
        }
        const int di = i / 7 - j / 7 + 6;
        const int dj = (i % 7) - (j % 7) + 6;
        Ss[e] = fmaf(s, scale, Bb[di * 13 + dj]);
    }
    __syncthreads();

    const int lane = tid & 31;
    const int warp = tid >> 5;
    for (int row = warp; row < P_; row += 8) {
        float* srow = Ss + row * 49;
        float v0 = srow[lane];
        float v1 = (lane + 32 < 49) ? srow[lane + 32] : -1e30f;
        float m = fmaxf(v0, v1);
#pragma unroll
        for (int o = 16; o; o >>= 1) m = fmaxf(m, __shfl_xor_sync(~0u, m, o));
        float e0 = __expf(v0 - m);
        float e1 = (lane + 32 < 49) ? __expf(v1 - m) : 0.f;
        float sum = e0 + e1;
#pragma unroll
        for (int o = 16; o; o >>= 1) sum += __shfl_xor_sync(~0u, sum, o);
        float inv = 1.f / sum;
        srow[lane] = e0 * inv;
        if (lane + 32 < 49) srow[lane + 32] = e1 * inv;
    }
    __syncthreads();

    for (int e = tid; e < P_ * HD_; e += 256) {
        const int i = e >> 5;
        const int d = e & 31;
        const float* prow = Ss + i * 49;
        const float* vcol = Vs + d;
        float o = 0.f;
#pragma unroll
        for (int j = 0; j < P_; j++) o = fmaf(prow[j], vcol[j * HD_], o);
        g_attn[(w * P_ + i) * C_ + h * HD_ + d] = o;
    }
}

// ---------------------------------------------------------------------------
extern "C" void kernel_launch(void* const* d_in, const int* in_sizes, int n_in,
                              void* d_out, int out_size) {
    (void)in_sizes; (void)n_in; (void)out_size;
    const float* x      = (const float*)d_in[0];
    const float* w_qkv  = (const float*)d_in[1];
    const float* b_qkv  = (const float*)d_in[2];
    const float* relpos = (const float*)d_in[3];
    const float* w_out  = (const float*)d_in[4];
    const float* b_out  = (const float*)d_in[5];
    float* out = (float*)d_out;

    prep_weights<<<2304, 256>>>(w_qkv, w_out);

    dim3 g1(TOK_ / BM, QKVN_ / BN);
    qkv_mma<<<g1, 256>>>(x, b_qkv);

    attn_kernel<<<BW_ * NH_, 256>>>(relpos);

    dim3 g3(TOK_ / BM, C_ / BN);
    proj_mma<<<g3, 256>>>(b_out, out);
}

// round 4
// speedup vs baseline: 1.3594x; 1.3219x over previous
#include <cuda_runtime.h>
#include <cuda_bf16.h>
#include <stdint.h>

#define C_    384
#define NH_   12
#define HD_   32
#define P_    49
#define BW_   2048
#define TOK_  100352
#define QKVN_ 1152

__device__ float g_q[BW_ * NH_ * P_ * HD_];
__device__ float g_k[BW_ * NH_ * P_ * HD_];
__device__ float g_v[BW_ * NH_ * P_ * HD_];
__device__ float g_attn[TOK_ * C_];
__device__ __nv_bfloat16 g_wqkvT_h[QKVN_ * C_];
__device__ __nv_bfloat16 g_wqkvT_l[QKVN_ * C_];
__device__ __nv_bfloat16 g_woutT_h[C_ * C_];
__device__ __nv_bfloat16 g_woutT_l[C_ * C_];

__device__ __forceinline__ int token_to_xoff(int t) {
    int b  = t / 3136;
    int r  = t - b * 3136;
    int w  = r / 49;
    int pp = r - w * 49;
    int wi = w >> 3, wj = w & 7;
    int pi = pp / 7, pj = pp - pi * 7;
    return ((b * 56 + wi * 7 + pi) * 56 + (wj * 7 + pj)) * 384;
}

__global__ void prep_weights(const float* __restrict__ wqkv,
                             const float* __restrict__ wout) {
    int idx = blockIdx.x * 256 + threadIdx.x;
    if (idx < QKVN_ * C_) {
        int n = idx / C_;
        int k = idx - n * C_;
        float v = wqkv[k * QKVN_ + n];
        __nv_bfloat16 h = __float2bfloat16(v);
        g_wqkvT_h[idx] = h;
        g_wqkvT_l[idx] = __float2bfloat16(v - __bfloat162float(h));
    } else {
        int j = idx - QKVN_ * C_;
        if (j < C_ * C_) {
            int n = j / C_;
            int k = j - n * C_;
            float v = wout[k * C_ + n];
            __nv_bfloat16 h = __float2bfloat16(v);
            g_woutT_h[j] = h;
            g_woutT_l[j] = __float2bfloat16(v - __bfloat162float(h));
        }
    }
}

__device__ __forceinline__ void ldm4(uint32_t* r, const __nv_bfloat16* p) {
    uint32_t addr = (uint32_t)__cvta_generic_to_shared(p);
    asm volatile("ldmatrix.sync.aligned.m8n8.x4.shared.b16 {%0,%1,%2,%3}, [%4];"
                 : "=r"(r[0]), "=r"(r[1]), "=r"(r[2]), "=r"(r[3]) : "r"(addr));
}

__device__ __forceinline__ void mma16816(float* c, const uint32_t* a, const uint32_t* b) {
    asm volatile("mma.sync.aligned.m16n8k16.row.col.f32.bf16.bf16.f32 "
                 "{%0,%1,%2,%3}, {%4,%5,%6,%7}, {%8,%9}, {%0,%1,%2,%3};"
                 : "+f"(c[0]), "+f"(c[1]), "+f"(c[2]), "+f"(c[3])
                 : "r"(a[0]), "r"(a[1]), "r"(a[2]), "r"(a[3]), "r"(b[0]), "r"(b[1]));
}

__device__ __forceinline__ void split_store8(float4 a, float4 b,
                                             __nv_bfloat16* dh, __nv_bfloat16* dl) {
    float f[8];
    f[0] = a.x; f[1] = a.y; f[2] = a.z; f[3] = a.w;
    f[4] = b.x; f[5] = b.y; f[6] = b.z; f[7] = b.w;
    uint32_t hw[4];
    uint32_t lw[4];
#pragma unroll
    for (int i = 0; i < 4; i++) {
        __nv_bfloat16 h0 = __float2bfloat16(f[2 * i]);
        __nv_bfloat16 h1 = __float2bfloat16(f[2 * i + 1]);
        __nv_bfloat16 l0 = __float2bfloat16(f[2 * i] - __bfloat162float(h0));
        __nv_bfloat16 l1 = __float2bfloat16(f[2 * i + 1] - __bfloat162float(h1));
        hw[i] = (uint32_t)__bfloat16_as_ushort(h0) | ((uint32_t)__bfloat16_as_ushort(h1) << 16);
        lw[i] = (uint32_t)__bfloat16_as_ushort(l0) | ((uint32_t)__bfloat16_as_ushort(l1) << 16);
    }
    uint4 H;
    uint4 L;
    H.x = hw[0]; H.y = hw[1]; H.z = hw[2]; H.w = hw[3];
    L.x = lw[0]; L.y = lw[1]; L.z = lw[2]; L.w = lw[3];
    *(uint4*)dh = H;
    *(uint4*)dl = L;
}

__device__ __forceinline__ void scatter_qkv2(int w, int pp, int n, float2 v) {
    int which = n / C_;
    int nn = n - which * C_;
    int head = nn >> 5;
    int d = nn & 31;
    float* dst = (which == 0) ? g_q : ((which == 1) ? g_k : g_v);
    *(float2*)&dst[((w * NH_ + head) * P_ + pp) * HD_ + d] = v;
}

#define BM 128
#define BN 128
#define BK 16
#define BKP 24

// ---------------------------------------------------------------------------
// Kernel 1: QKV GEMM. CTA 128x128, 8 warps, warp tile 64x32.
// ---------------------------------------------------------------------------
__global__ __launch_bounds__(256) void qkv_mma(const float* __restrict__ x,
                                               const float* __restrict__ bias) {
    __shared__ __nv_bfloat16 AsH[2][BM][BKP];
    __shared__ __nv_bfloat16 AsL[2][BM][BKP];
    __shared__ __nv_bfloat16 BsH[2][BN][BKP];
    __shared__ __nv_bfloat16 BsL[2][BN][BKP];

    const int tid = threadIdx.x;
    const int m0 = blockIdx.x * BM;
    const int n0 = blockIdx.y * BN;

    // A loader: 256 threads cover 128 rows x 16 k (8 k per thread)
    const int arow  = tid >> 1;
    const int akoff = (tid & 1) * 8;
    const float* aptr = x + token_to_xoff(m0 + arow) + akoff;

    // B loader: tid<128 -> hi, tid>=128 -> lo. Each thread: rows brow, brow+64 (8 k each)
    const int bhalf = tid >> 7;
    const int t2    = tid & 127;
    const int brow  = t2 >> 1;
    const int bkoff = (t2 & 1) * 8;
    const __nv_bfloat16* bptr =
        (bhalf ? g_wqkvT_l : g_wqkvT_h) + (n0 + brow) * C_ + bkoff;

    const int warp = tid >> 5;
    const int lane = tid & 31;
    const int wm = (warp >> 2) * 64;
    const int wn = (warp & 3) * 32;
    const int grp = lane >> 3;
    const int lr = lane & 7;
    const int a_r = (grp & 1) * 8 + lr;
    const int a_k = (grp >> 1) * 8;
    const int b_r = (grp >> 1) * 8 + lr;
    const int b_k = (grp & 1) * 8;

    float acc[4][4][4];
#pragma unroll
    for (int i = 0; i < 4; i++) {
#pragma unroll
        for (int j = 0; j < 4; j++) {
#pragma unroll
            for (int e = 0; e < 4; e++) acc[i][j][e] = 0.f;
        }
    }

    float4 fa0 = *(const float4*)(aptr);
    float4 fa1 = *(const float4*)(aptr + 4);
    uint4 rb0 = *(const uint4*)(bptr);
    uint4 rb1 = *(const uint4*)(bptr + 64 * C_);

    split_store8(fa0, fa1, &AsH[0][arow][akoff], &AsL[0][arow][akoff]);
    if (bhalf == 0) {
        *(uint4*)&BsH[0][brow][bkoff] = rb0;
        *(uint4*)&BsH[0][brow + 64][bkoff] = rb1;
    } else {
        *(uint4*)&BsL[0][brow][bkoff] = rb0;
        *(uint4*)&BsL[0][brow + 64][bkoff] = rb1;
    }
    __syncthreads();

    const int NT = C_ / BK;
    for (int kt = 0; kt < NT; kt++) {
        const int cur = kt & 1;
        if (kt + 1 < NT) {
            const int kg = (kt + 1) * BK;
            fa0 = *(const float4*)(aptr + kg);
            fa1 = *(const float4*)(aptr + kg + 4);
            rb0 = *(const uint4*)(bptr + kg);
            rb1 = *(const uint4*)(bptr + kg + 64 * C_);
        }

        uint32_t ah[4][4];
        uint32_t al[4][4];
        uint32_t bh[4][2];
        uint32_t bl[4][2];
#pragma unroll
        for (int i = 0; i < 4; i++) {
            ldm4(ah[i], &AsH[cur][wm + i * 16 + a_r][a_k]);
            ldm4(al[i], &AsL[cur][wm + i * 16 + a_r][a_k]);
        }
#pragma unroll
        for (int q = 0; q < 2; q++) {
            uint32_t t[4];
            ldm4(t, &BsH[cur][wn + q * 16 + b_r][b_k]);
            bh[q * 2][0] = t[0]; bh[q * 2][1] = t[1];
            bh[q * 2 + 1][0] = t[2]; bh[q * 2 + 1][1] = t[3];
            ldm4(t, &BsL[cur][wn + q * 16 + b_r][b_k]);
            bl[q * 2][0] = t[0]; bl[q * 2][1] = t[1];
            bl[q * 2 + 1][0] = t[2]; bl[q * 2 + 1][1] = t[3];
        }

#pragma unroll
        for (int i = 0; i < 4; i++) {
#pragma unroll
            for (int j = 0; j < 4; j++) {
                mma16816(acc[i][j], ah[i], bh[j]);
                mma16816(acc[i][j], ah[i], bl[j]);
                mma16816(acc[i][j], al[i], bh[j]);
            }
        }

        if (kt + 1 < NT) {
            const int nxt = cur ^ 1;
            split_store8(fa0, fa1, &AsH[nxt][arow][akoff], &AsL[nxt][arow][akoff]);
            if (bhalf == 0) {
                *(uint4*)&BsH[nxt][brow][bkoff] = rb0;
                *(uint4*)&BsH[nxt][brow + 64][bkoff] = rb1;
            } else {
                *(uint4*)&BsL[nxt][brow][bkoff] = rb0;
                *(uint4*)&BsL[nxt][brow + 64][bkoff] = rb1;
            }
            __syncthreads();
        }
    }

    const int gid = lane >> 2;
    const int ctid = lane & 3;
#pragma unroll
    for (int i = 0; i < 4; i++) {
        const int r0 = m0 + wm + i * 16 + gid;
        const int r1 = r0 + 8;
        const int w0 = r0 / 49;
        const int p0 = r0 - w0 * 49;
        const int w1 = r1 / 49;
        const int p1 = r1 - w1 * 49;
#pragma unroll
        for (int j = 0; j < 4; j++) {
            const int n = n0 + wn + j * 8 + 2 * ctid;
            const float bz0 = __ldg(&bias[n]);
            const float bz1 = __ldg(&bias[n + 1]);
            float2 v0;
            float2 v1;
            v0.x = acc[i][j][0] + bz0;
            v0.y = acc[i][j][1] + bz1;
            v1.x = acc[i][j][2] + bz0;
            v1.y = acc[i][j][3] + bz1;
            scatter_qkv2(w0, p0, n, v0);
            scatter_qkv2(w1, p1, n, v1);
        }
    }
}

// ---------------------------------------------------------------------------
// Kernel 3: output projection GEMM. Same tiling, A = g_attn, N = 384.
// ---------------------------------------------------------------------------
__global__ __launch_bounds__(256) void proj_mma(const float* __restrict__ bias,
                                                float* __restrict__ outp) {
    __shared__ __nv_bfloat16 AsH[2][BM][BKP];
    __shared__ __nv_bfloat16 AsL[2][BM][BKP];
    __shared__ __nv_bfloat16 BsH[2][BN][BKP];
    __shared__ __nv_bfloat16 BsL[2][BN][BKP];

    const int tid = threadIdx.x;
    const int m0 = blockIdx.x * BM;
    const int n0 = blockIdx.y * BN;

    const int arow  = tid >> 1;
    const int akoff = (tid & 1) * 8;
    const float* aptr = g_attn + (m0 + arow) * C_ + akoff;

    const int bhalf = tid >> 7;
    const int t2    = tid & 127;
    const int brow  = t2 >> 1;
    const int bkoff = (t2 & 1) * 8;
    const __nv_bfloat16* bptr =
        (bhalf ? g_woutT_l : g_woutT_h) + (n0 + brow) * C_ + bkoff;

    const int warp = tid >> 5;
    const int lane = tid & 31;
    const int wm = (warp >> 2) * 64;
    const int wn = (warp & 3) * 32;
    const int grp = lane >> 3;
    const int lr = lane & 7;
    const int a_r = (grp & 1) * 8 + lr;
    const int a_k = (grp >> 1) * 8;
    const int b_r = (grp >> 1) * 8 + lr;
    const int b_k = (grp & 1) * 8;

    float acc[4][4][4];
#pragma unroll
    for (int i = 0; i < 4; i++) {
#pragma unroll
        for (int j = 0; j < 4; j++) {
#pragma unroll
            for (int e = 0; e < 4; e++) acc[i][j][e] = 0.f;
        }
    }

    float4 fa0 = *(const float4*)(aptr);
    float4 fa1 = *(const float4*)(aptr + 4);
    uint4 rb0 = *(const uint4*)(bptr);
    uint4 rb1 = *(const uint4*)(bptr + 64 * C_);

    split_store8(fa0, fa1, &AsH[0][arow][akoff], &AsL[0][arow][akoff]);
    if (bhalf == 0) {
        *(uint4*)&BsH[0][brow][bkoff] = rb0;
        *(uint4*)&BsH[0][brow + 64][bkoff] = rb1;
    } else {
        *(uint4*)&BsL[0][brow][bkoff] = rb0;
        *(uint4*)&BsL[0][brow + 64][bkoff] = rb1;
    }
    __syncthreads();

    const int NT = C_ / BK;
    for (int kt = 0; kt < NT; kt++) {
        const int cur = kt & 1;
        if (kt + 1 < NT) {
            const int kg = (kt + 1) * BK;
            fa0 = *(const float4*)(aptr + kg);
            fa1 = *(const float4*)(aptr + kg + 4);
            rb0 = *(const uint4*)(bptr + kg);
            rb1 = *(const uint4*)(bptr + kg + 64 * C_);
        }

        uint32_t ah[4][4];
        uint32_t al[4][4];
        uint32_t bh[4][2];
        uint32_t bl[4][2];
#pragma unroll
        for (int i = 0; i < 4; i++) {
            ldm4(ah[i], &AsH[cur][wm + i * 16 + a_r][a_k]);
            ldm4(al[i], &AsL[cur][wm + i * 16 + a_r][a_k]);
        }
#pragma unroll
        for (int q = 0; q < 2; q++) {
            uint32_t t[4];
            ldm4(t, &BsH[cur][wn + q * 16 + b_r][b_k]);
            bh[q * 2][0] = t[0]; bh[q * 2][1] = t[1];
            bh[q * 2 + 1][0] = t[2]; bh[q * 2 + 1][1] = t[3];
            ldm4(t, &BsL[cur][wn + q * 16 + b_r][b_k]);
            bl[q * 2][0] = t[0]; bl[q * 2][1] = t[1];
            bl[q * 2 + 1][0] = t[2]; bl[q * 2 + 1][1] = t[3];
        }

#pragma unroll
        for (int i = 0; i < 4; i++) {
#pragma unroll
            for (int j = 0; j < 4; j++) {
                mma16816(acc[i][j], ah[i], bh[j]);
                mma16816(acc[i][j], ah[i], bl[j]);
                mma16816(acc[i][j], al[i], bh[j]);
            }
        }

        if (kt + 1 < NT) {
            const int nxt = cur ^ 1;
            split_store8(fa0, fa1, &AsH[nxt][arow][akoff], &AsL[nxt][arow][akoff]);
            if (bhalf == 0) {
                *(uint4*)&BsH[nxt][brow][bkoff] = rb0;
                *(uint4*)&BsH[nxt][brow + 64][bkoff] = rb1;
            } else {
                *(uint4*)&BsL[nxt][brow][bkoff] = rb0;
                *(uint4*)&BsL[nxt][brow + 64][bkoff] = rb1;
            }
            __syncthreads();
        }
    }

    const int gid = lane >> 2;
    const int ctid = lane & 3;
#pragma unroll
    for (int i = 0; i < 4; i++) {
        const int r0 = m0 + wm + i * 16 + gid;
        const int r1 = r0 + 8;
        const int x0 = token_to_xoff(r0);
        const int x1 = token_to_xoff(r1);
#pragma unroll
        for (int j = 0; j < 4; j++) {
            const int n = n0 + wn + j * 8 + 2 * ctid;
            const float bz0 = __ldg(&bias[n]);
            const float bz1 = __ldg(&bias[n + 1]);
            float2 v0;
            float2 v1;
            v0.x = acc[i][j][0] + bz0;
            v0.y = acc[i][j][1] + bz1;
            v1.x = acc[i][j][2] + bz0;
            v1.y = acc[i][j][3] + bz1;
            *(float2*)&outp[x0 + n] = v0;
            *(float2*)&outp[x1 + n] = v1;
        }
    }
}

// ---------------------------------------------------------------------------
// Kernel 2: per (window, head) attention — unchanged (proven)
// ---------------------------------------------------------------------------
__global__ __launch_bounds__(256) void attn_kernel(const float* __restrict__ rel_pos) {
    const int wh = blockIdx.x;
    const int h  = wh % NH_;
    const int w  = wh / NH_;
    const int tid = threadIdx.x;

    __shared__ float Qs[P_ * HD_];
    __shared__ float Ks[P_ * HD_];
    __shared__ float Vs[P_ * HD_];
    __shared__ float Ss[P_ * P_];
    __shared__ float Bb[13 * 13];

    const float4* qg = (const float4*)(g_q + wh * (P_ * HD_));
    const float4* kg = (const float4*)(g_k + wh * (P_ * HD_));
    const float4* vg = (const float4*)(g_v + wh * (P_ * HD_));
    for (int idx = tid; idx < (P_ * HD_) / 4; idx += 256) {
        ((float4*)Qs)[idx] = qg[idx];
        ((float4*)Ks)[idx] = kg[idx];
        ((float4*)Vs)[idx] = vg[idx];
    }
    if (tid < 169) Bb[tid] = rel_pos[h * 169 + tid];
    __syncthreads();

    const float scale = 0.17677669529663687f;

    for (int e = tid; e < P_ * P_; e += 256) {
        const int i = e / 49;
        const int j = e - i * 49;
        const float4* qa = (const float4*)(Qs + i * HD_);
        const float4* kb = (const float4*)(Ks + j * HD_);
        float s = 0.f;
#pragma unroll
        for (int u = 0; u < HD_ / 4; u++) {
            float4 a = qa[u];
            float4 b = kb[u];
            s = fmaf(a.x, b.x, s);
            s = fmaf(a.y, b.y, s);
            s = fmaf(a.z, b.z, s);
            s = fmaf(a.w, b.w, s);
        }
        const int di = i / 7 - j / 7 + 6;
        const int dj = (i % 7) - (j % 7) + 6;
        Ss[e] = fmaf(s, scale, Bb[di * 13 + dj]);
    }
    __syncthreads();

    const int lane = tid & 31;
    const int warp = tid >> 5;
    for (int row = warp; row < P_; row += 8) {
        float* srow = Ss + row * 49;
        float v0 = srow[lane];
        float v1 = (lane + 32 < 49) ? srow[lane + 32] : -1e30f;
        float m = fmaxf(v0, v1);
#pragma unroll
        for (int o = 16; o; o >>= 1) m = fmaxf(m, __shfl_xor_sync(~0u, m, o));
        float e0 = __expf(v0 - m);
        float e1 = (lane + 32 < 49) ? __expf(v1 - m) : 0.f;
        float sum = e0 + e1;
#pragma unroll
        for (int o = 16; o; o >>= 1) sum += __shfl_xor_sync(~0u, sum, o);
        float inv = 1.f / sum;
        srow[lane] = e0 * inv;
        if (lane + 32 < 49) srow[lane + 32] = e1 * inv;
    }
    __syncthreads();

    for (int e = tid; e < P_ * HD_; e += 256) {
        const int i = e >> 5;
        const int d = e & 31;
        const float* prow = Ss + i * 49;
        const float* vcol = Vs + d;
        float o = 0.f;
#pragma unroll
        for (int j = 0; j < P_; j++) o = fmaf(prow[j], vcol[j * HD_], o);
        g_attn[(w * P_ + i) * C_ + h * HD_ + d] = o;
    }
}

// ---------------------------------------------------------------------------
extern "C" void kernel_launch(void* const* d_in, const int* in_sizes, int n_in,
                              void* d_out, int out_size) {
    (void)in_sizes; (void)n_in; (void)out_size;
    const float* x      = (const float*)d_in[0];
    const float* w_qkv  = (const float*)d_in[1];
    const float* b_qkv  = (const float*)d_in[2];
    const float* relpos = (const float*)d_in[3];
    const float* w_out  = (const float*)d_in[4];
    const float* b_out  = (const float*)d_in[5];
    float* out = (float*)d_out;

    prep_weights<<<2304, 256>>>(w_qkv, w_out);

    dim3 g1(TOK_ / BM, QKVN_ / BN);   // 784 x 9
    qkv_mma<<<g1, 256>>>(x, b_qkv);

    attn_kernel<<<BW_ * NH_, 256>>>(relpos);

    dim3 g3(TOK_ / BM, C_ / BN);      // 784 x 3
    proj_mma<<<g3, 256>>>(b_out, out);
}

// round 6
// speedup vs baseline: 2.8855x; 2.1226x over previous
#include <cuda_runtime.h>
#include <cuda_bf16.h>
#include <stdint.h>

#define C_    384
#define NH_   12
#define HD_   32
#define P_    49
#define BW_   2048
#define TOK_  100352
#define QKVN_ 1152

__device__ float g_attn[TOK_ * C_];
__device__ __nv_bfloat16 g_qh[BW_ * NH_ * P_ * HD_];
__device__ __nv_bfloat16 g_ql[BW_ * NH_ * P_ * HD_];
__device__ __nv_bfloat16 g_kh[BW_ * NH_ * P_ * HD_];
__device__ __nv_bfloat16 g_kl[BW_ * NH_ * P_ * HD_];
__device__ __nv_bfloat16 g_vh[BW_ * NH_ * P_ * HD_];
__device__ __nv_bfloat16 g_vl[BW_ * NH_ * P_ * HD_];
__device__ __nv_bfloat16 g_wqkvT_h[QKVN_ * C_];
__device__ __nv_bfloat16 g_wqkvT_l[QKVN_ * C_];
__device__ __nv_bfloat16 g_woutT_h[C_ * C_];
__device__ __nv_bfloat16 g_woutT_l[C_ * C_];

__device__ __forceinline__ int token_to_xoff(int t) {
    int b  = t / 3136;
    int r  = t - b * 3136;
    int w  = r / 49;
    int pp = r - w * 49;
    int wi = w >> 3, wj = w & 7;
    int pi = pp / 7, pj = pp - pi * 7;
    return ((b * 56 + wi * 7 + pi) * 56 + (wj * 7 + pj)) * 384;
}

__global__ void prep_weights(const float* __restrict__ wqkv,
                             const float* __restrict__ wout) {
    int idx = blockIdx.x * 256 + threadIdx.x;
    if (idx < QKVN_ * C_) {
        int n = idx / C_;
        int k = idx - n * C_;
        float v = wqkv[k * QKVN_ + n];
        __nv_bfloat16 h = __float2bfloat16(v);
        g_wqkvT_h[idx] = h;
        g_wqkvT_l[idx] = __float2bfloat16(v - __bfloat162float(h));
    } else {
        int j = idx - QKVN_ * C_;
        if (j < C_ * C_) {
            int n = j / C_;
            int k = j - n * C_;
            float v = wout[k * C_ + n];
            __nv_bfloat16 h = __float2bfloat16(v);
            g_woutT_h[j] = h;
            g_woutT_l[j] = __float2bfloat16(v - __bfloat162float(h));
        }
    }
}

__device__ __forceinline__ void ldm4(uint32_t* r, const __nv_bfloat16* p) {
    uint32_t addr = (uint32_t)__cvta_generic_to_shared(p);
    asm volatile("ldmatrix.sync.aligned.m8n8.x4.shared.b16 {%0,%1,%2,%3}, [%4];"
                 : "=r"(r[0]), "=r"(r[1]), "=r"(r[2]), "=r"(r[3]) : "r"(addr));
}

__device__ __forceinline__ void mma16816(float* c, const uint32_t* a, const uint32_t* b) {
    asm volatile("mma.sync.aligned.m16n8k16.row.col.f32.bf16.bf16.f32 "
                 "{%0,%1,%2,%3}, {%4,%5,%6,%7}, {%8,%9}, {%0,%1,%2,%3};"
                 : "+f"(c[0]), "+f"(c[1]), "+f"(c[2]), "+f"(c[3])
                 : "r"(a[0]), "r"(a[1]), "r"(a[2]), "r"(a[3]), "r"(b[0]), "r"(b[1]));
}

__device__ __forceinline__ void split_store8(float4 a, float4 b,
                                             __nv_bfloat16* dh, __nv_bfloat16* dl) {
    float f[8];
    f[0] = a.x; f[1] = a.y; f[2] = a.z; f[3] = a.w;
    f[4] = b.x; f[5] = b.y; f[6] = b.z; f[7] = b.w;
    uint32_t hw[4];
    uint32_t lw[4];
#pragma unroll
    for (int i = 0; i < 4; i++) {
        __nv_bfloat16 h0 = __float2bfloat16(f[2 * i]);
        __nv_bfloat16 h1 = __float2bfloat16(f[2 * i + 1]);
        __nv_bfloat16 l0 = __float2bfloat16(f[2 * i] - __bfloat162float(h0));
        __nv_bfloat16 l1 = __float2bfloat16(f[2 * i + 1] - __bfloat162float(h1));
        hw[i] = (uint32_t)__bfloat16_as_ushort(h0) | ((uint32_t)__bfloat16_as_ushort(h1) << 16);
        lw[i] = (uint32_t)__bfloat16_as_ushort(l0) | ((uint32_t)__bfloat16_as_ushort(l1) << 16);
    }
    uint4 H;
    uint4 L;
    H.x = hw[0]; H.y = hw[1]; H.z = hw[2]; H.w = hw[3];
    L.x = lw[0]; L.y = lw[1]; L.z = lw[2]; L.w = lw[3];
    *(uint4*)dh = H;
    *(uint4*)dl = L;
}

__device__ __forceinline__ uint32_t pack_hi2(float x, float y) {
    __nv_bfloat16 hx = __float2bfloat16(x);
    __nv_bfloat16 hy = __float2bfloat16(y);
    return (uint32_t)__bfloat16_as_ushort(hx) | ((uint32_t)__bfloat16_as_ushort(hy) << 16);
}

__device__ __forceinline__ uint32_t pack_lo2(float x, float y) {
    __nv_bfloat16 hx = __float2bfloat16(x);
    __nv_bfloat16 hy = __float2bfloat16(y);
    __nv_bfloat16 lx = __float2bfloat16(x - __bfloat162float(hx));
    __nv_bfloat16 ly = __float2bfloat16(y - __bfloat162float(hy));
    return (uint32_t)__bfloat16_as_ushort(lx) | ((uint32_t)__bfloat16_as_ushort(ly) << 16);
}

__device__ __forceinline__ void scatter_qkv_bf(int w, int pp, int n, float vx, float vy) {
    int which = n / C_;
    int nn = n - which * C_;
    int head = nn >> 5;
    int d = nn & 31;
    __nv_bfloat16* dh;
    __nv_bfloat16* dl;
    if (which == 0)      { dh = g_qh; dl = g_ql; }
    else if (which == 1) { dh = g_kh; dl = g_kl; }
    else                 { dh = g_vh; dl = g_vl; }
    int off = ((w * NH_ + head) * P_ + pp) * HD_ + d;
    *(uint32_t*)&dh[off] = pack_hi2(vx, vy);
    *(uint32_t*)&dl[off] = pack_lo2(vx, vy);
}

#define BM 128
#define BN 128
#define BK 16
#define BKP 24

// ---------------------------------------------------------------------------
// Kernel 1: QKV GEMM. CTA 128x128, 8 warps, warp tile 64x32.
// ---------------------------------------------------------------------------
__global__ __launch_bounds__(256) void qkv_mma(const float* __restrict__ x,
                                               const float* __restrict__ bias) {
    __shared__ __nv_bfloat16 AsH[2][BM][BKP];
    __shared__ __nv_bfloat16 AsL[2][BM][BKP];
    __shared__ __nv_bfloat16 BsH[2][BN][BKP];
    __shared__ __nv_bfloat16 BsL[2][BN][BKP];

    const int tid = threadIdx.x;
    const int m0 = blockIdx.x * BM;
    const int n0 = blockIdx.y * BN;

    const int arow  = tid >> 1;
    const int akoff = (tid & 1) * 8;
    const float* aptr = x + token_to_xoff(m0 + arow) + akoff;

    const int bhalf = tid >> 7;
    const int t2    = tid & 127;
    const int brow  = t2 >> 1;
    const int bkoff = (t2 & 1) * 8;
    const __nv_bfloat16* bptr =
        (bhalf ? g_wqkvT_l : g_wqkvT_h) + (n0 + brow) * C_ + bkoff;

    const int warp = tid >> 5;
    const int lane = tid & 31;
    const int wm = (warp >> 2) * 64;
    const int wn = (warp & 3) * 32;
    const int grp = lane >> 3;
    const int lr = lane & 7;
    const int a_r = (grp & 1) * 8 + lr;
    const int a_k = (grp >> 1) * 8;
    const int b_r = (grp >> 1) * 8 + lr;
    const int b_k = (grp & 1) * 8;

    float acc[4][4][4];
#pragma unroll
    for (int i = 0; i < 4; i++) {
#pragma unroll
        for (int j = 0; j < 4; j++) {
#pragma unroll
            for (int e = 0; e < 4; e++) acc[i][j][e] = 0.f;
        }
    }

    float4 fa0 = *(const float4*)(aptr);
    float4 fa1 = *(const float4*)(aptr + 4);
    uint4 rb0 = *(const uint4*)(bptr);
    uint4 rb1 = *(const uint4*)(bptr + 64 * C_);

    split_store8(fa0, fa1, &AsH[0][arow][akoff], &AsL[0][arow][akoff]);
    if (bhalf == 0) {
        *(uint4*)&BsH[0][brow][bkoff] = rb0;
        *(uint4*)&BsH[0][brow + 64][bkoff] = rb1;
    } else {
        *(uint4*)&BsL[0][brow][bkoff] = rb0;
        *(uint4*)&BsL[0][brow + 64][bkoff] = rb1;
    }
    __syncthreads();

    const int NT = C_ / BK;
    for (int kt = 0; kt < NT; kt++) {
        const int cur = kt & 1;
        if (kt + 1 < NT) {
            const int kg = (kt + 1) * BK;
            fa0 = *(const float4*)(aptr + kg);
            fa1 = *(const float4*)(aptr + kg + 4);
            rb0 = *(const uint4*)(bptr + kg);
            rb1 = *(const uint4*)(bptr + kg + 64 * C_);
        }

        uint32_t ah[4][4];
        uint32_t al[4][4];
        uint32_t bh[4][2];
        uint32_t bl[4][2];
#pragma unroll
        for (int i = 0; i < 4; i++) {
            ldm4(ah[i], &AsH[cur][wm + i * 16 + a_r][a_k]);
            ldm4(al[i], &AsL[cur][wm + i * 16 + a_r][a_k]);
        }
#pragma unroll
        for (int q = 0; q < 2; q++) {
            uint32_t t[4];
            ldm4(t, &BsH[cur][wn + q * 16 + b_r][b_k]);
            bh[q * 2][0] = t[0]; bh[q * 2][1] = t[1];
            bh[q * 2 + 1][0] = t[2]; bh[q * 2 + 1][1] = t[3];
            ldm4(t, &BsL[cur][wn + q * 16 + b_r][b_k]);
            bl[q * 2][0] = t[0]; bl[q * 2][1] = t[1];
            bl[q * 2 + 1][0] = t[2]; bl[q * 2 + 1][1] = t[3];
        }

#pragma unroll
        for (int i = 0; i < 4; i++) {
#pragma unroll
            for (int j = 0; j < 4; j++) {
                mma16816(acc[i][j], ah[i], bh[j]);
                mma16816(acc[i][j], ah[i], bl[j]);
                mma16816(acc[i][j], al[i], bh[j]);
            }
        }

        if (kt + 1 < NT) {
            const int nxt = cur ^ 1;
            split_store8(fa0, fa1, &AsH[nxt][arow][akoff], &AsL[nxt][arow][akoff]);
            if (bhalf == 0) {
                *(uint4*)&BsH[nxt][brow][bkoff] = rb0;
                *(uint4*)&BsH[nxt][brow + 64][bkoff] = rb1;
            } else {
                *(uint4*)&BsL[nxt][brow][bkoff] = rb0;
                *(uint4*)&BsL[nxt][brow + 64][bkoff] = rb1;
            }
            __syncthreads();
        }
    }

    const int gid = lane >> 2;
    const int ctid = lane & 3;
#pragma unroll
    for (int i = 0; i < 4; i++) {
        const int r0 = m0 + wm + i * 16 + gid;
        const int r1 = r0 + 8;
        const int w0 = r0 / 49;
        const int p0 = r0 - w0 * 49;
        const int w1 = r1 / 49;
        const int p1 = r1 - w1 * 49;
#pragma unroll
        for (int j = 0; j < 4; j++) {
            const int n = n0 + wn + j * 8 + 2 * ctid;
            const float bz0 = __ldg(&bias[n]);
            const float bz1 = __ldg(&bias[n + 1]);
            scatter_qkv_bf(w0, p0, n, acc[i][j][0] + bz0, acc[i][j][1] + bz1);
            scatter_qkv_bf(w1, p1, n, acc[i][j][2] + bz0, acc[i][j][3] + bz1);
        }
    }
}

// ---------------------------------------------------------------------------
// Kernel 3: output projection GEMM
// ---------------------------------------------------------------------------
__global__ __launch_bounds__(256) void proj_mma(const float* __restrict__ bias,
                                                float* __restrict__ outp) {
    __shared__ __nv_bfloat16 AsH[2][BM][BKP];
    __shared__ __nv_bfloat16 AsL[2][BM][BKP];
    __shared__ __nv_bfloat16 BsH[2][BN][BKP];
    __shared__ __nv_bfloat16 BsL[2][BN][BKP];

    const int tid = threadIdx.x;
    const int m0 = blockIdx.x * BM;
    const int n0 = blockIdx.y * BN;

    const int arow  = tid >> 1;
    const int akoff = (tid & 1) * 8;
    const float* aptr = g_attn + (m0 + arow) * C_ + akoff;

    const int bhalf = tid >> 7;
    const int t2    = tid & 127;
    const int brow  = t2 >> 1;
    const int bkoff = (t2 & 1) * 8;
    const __nv_bfloat16* bptr =
        (bhalf ? g_woutT_l : g_woutT_h) + (n0 + brow) * C_ + bkoff;

    const int warp = tid >> 5;
    const int lane = tid & 31;
    const int wm = (warp >> 2) * 64;
    const int wn = (warp & 3) * 32;
    const int grp = lane >> 3;
    const int lr = lane & 7;
    const int a_r = (grp & 1) * 8 + lr;
    const int a_k = (grp >> 1) * 8;
    const int b_r = (grp >> 1) * 8 + lr;
    const int b_k = (grp & 1) * 8;

    float acc[4][4][4];
#pragma unroll
    for (int i = 0; i < 4; i++) {
#pragma unroll
        for (int j = 0; j < 4; j++) {
#pragma unroll
            for (int e = 0; e < 4; e++) acc[i][j][e] = 0.f;
        }
    }

    float4 fa0 = *(const float4*)(aptr);
    float4 fa1 = *(const float4*)(aptr + 4);
    uint4 rb0 = *(const uint4*)(bptr);
    uint4 rb1 = *(const uint4*)(bptr + 64 * C_);

    split_store8(fa0, fa1, &AsH[0][arow][akoff], &AsL[0][arow][akoff]);
    if (bhalf == 0) {
        *(uint4*)&BsH[0][brow][bkoff] = rb0;
        *(uint4*)&BsH[0][brow + 64][bkoff] = rb1;
    } else {
        *(uint4*)&BsL[0][brow][bkoff] = rb0;
        *(uint4*)&BsL[0][brow + 64][bkoff] = rb1;
    }
    __syncthreads();

    const int NT = C_ / BK;
    for (int kt = 0; kt < NT; kt++) {
        const int cur = kt & 1;
        if (kt + 1 < NT) {
            const int kg = (kt + 1) * BK;
            fa0 = *(const float4*)(aptr + kg);
            fa1 = *(const float4*)(aptr + kg + 4);
            rb0 = *(const uint4*)(bptr + kg);
            rb1 = *(const uint4*)(bptr + kg + 64 * C_);
        }

        uint32_t ah[4][4];
        uint32_t al[4][4];
        uint32_t bh[4][2];
        uint32_t bl[4][2];
#pragma unroll
        for (int i = 0; i < 4; i++) {
            ldm4(ah[i], &AsH[cur][wm + i * 16 + a_r][a_k]);
            ldm4(al[i], &AsL[cur][wm + i * 16 + a_r][a_k]);
        }
#pragma unroll
        for (int q = 0; q < 2; q++) {
            uint32_t t[4];
            ldm4(t, &BsH[cur][wn + q * 16 + b_r][b_k]);
            bh[q * 2][0] = t[0]; bh[q * 2][1] = t[1];
            bh[q * 2 + 1][0] = t[2]; bh[q * 2 + 1][1] = t[3];
            ldm4(t, &BsL[cur][wn + q * 16 + b_r][b_k]);
            bl[q * 2][0] = t[0]; bl[q * 2][1] = t[1];
            bl[q * 2 + 1][0] = t[2]; bl[q * 2 + 1][1] = t[3];
        }

#pragma unroll
        for (int i = 0; i < 4; i++) {
#pragma unroll
            for (int j = 0; j < 4; j++) {
                mma16816(acc[i][j], ah[i], bh[j]);
                mma16816(acc[i][j], ah[i], bl[j]);
                mma16816(acc[i][j], al[i], bh[j]);
            }
        }

        if (kt + 1 < NT) {
            const int nxt = cur ^ 1;
            split_store8(fa0, fa1, &AsH[nxt][arow][akoff], &AsL[nxt][arow][akoff]);
            if (bhalf == 0) {
                *(uint4*)&BsH[nxt][brow][bkoff] = rb0;
                *(uint4*)&BsH[nxt][brow + 64][bkoff] = rb1;
            } else {
                *(uint4*)&BsL[nxt][brow][bkoff] = rb0;
                *(uint4*)&BsL[nxt][brow + 64][bkoff] = rb1;
            }
            __syncthreads();
        }
    }

    const int gid = lane >> 2;
    const int ctid = lane & 3;
#pragma unroll
    for (int i = 0; i < 4; i++) {
        const int r0 = m0 + wm + i * 16 + gid;
        const int r1 = r0 + 8;
        const int x0 = token_to_xoff(r0);
        const int x1 = token_to_xoff(r1);
#pragma unroll
        for (int j = 0; j < 4; j++) {
            const int n = n0 + wn + j * 8 + 2 * ctid;
            const float bz0 = __ldg(&bias[n]);
            const float bz1 = __ldg(&bias[n + 1]);
            float2 v0;
            float2 v1;
            v0.x = acc[i][j][0] + bz0;
            v0.y = acc[i][j][1] + bz1;
            v1.x = acc[i][j][2] + bz0;
            v1.y = acc[i][j][3] + bz1;
            *(float2*)&outp[x0 + n] = v0;
            *(float2*)&outp[x1 + n] = v1;
        }
    }
}

// ---------------------------------------------------------------------------
// Kernel 2: tensor-core attention. 1 CTA = 1 (window, head), 4 warps.
// ---------------------------------------------------------------------------
#define QKS 40
#define VTS 72

__global__ __launch_bounds__(128) void attn_mma(const float* __restrict__ rel_pos) {
    const int wh = blockIdx.x;
    const int h  = wh % NH_;
    const int w  = wh / NH_;
    const int tid = threadIdx.x;
    const int warp = tid >> 5;
    const int lane = tid & 31;

    __shared__ __nv_bfloat16 Qh[64 * QKS];
    __shared__ __nv_bfloat16 Ql[64 * QKS];
    __shared__ __nv_bfloat16 Kh[64 * QKS];
    __shared__ __nv_bfloat16 Kl[64 * QKS];
    __shared__ __nv_bfloat16 Vth[32 * VTS];
    __shared__ __nv_bfloat16 Vtl[32 * VTS];
    __shared__ float Bb[169];

    const int base = wh * (P_ * HD_);

    // zero Vt pads
    for (int e = tid; e < 32 * VTS; e += 128) {
        ((ushort*)Vth)[e] = 0;
        ((ushort*)Vtl)[e] = 0;
    }
    __syncthreads();

    for (int e = tid; e < 49 * 4; e += 128) {
        const int p = e >> 2;
        const int ch = (e & 3) * 8;
        *(uint4*)&Qh[p * QKS + ch] = *(const uint4*)&g_qh[base + p * 32 + ch];
        *(uint4*)&Ql[p * QKS + ch] = *(const uint4*)&g_ql[base + p * 32 + ch];
        *(uint4*)&Kh[p * QKS + ch] = *(const uint4*)&g_kh[base + p * 32 + ch];
        *(uint4*)&Kl[p * QKS + ch] = *(const uint4*)&g_kl[base + p * 32 + ch];
    }
    for (int e = tid; e < 49 * 32; e += 128) {
        const int p = e >> 5;
        const int d = e & 31;
        Vth[d * VTS + p] = g_vh[base + e];
        Vtl[d * VTS + p] = g_vl[base + e];
    }
    // FIX (R5 bug): 128 threads must cover all 169 bias entries
    for (int e = tid; e < 169; e += 128) Bb[e] = rel_pos[h * 169 + e];
    __syncthreads();

    const int grp = lane >> 3;
    const int lr = lane & 7;
    const int a_r = (grp & 1) * 8 + lr;
    const int a_k = (grp >> 1) * 8;
    const int b_r = (grp >> 1) * 8 + lr;
    const int b_k = (grp & 1) * 8;
    const int gid = lane >> 2;
    const int ctid = lane & 3;

    // ---- S = Q K^T ----
    float accS[8][4];
#pragma unroll
    for (int t = 0; t < 8; t++) {
#pragma unroll
        for (int e = 0; e < 4; e++) accS[t][e] = 0.f;
    }

#pragma unroll
    for (int ko = 0; ko < 32; ko += 16) {
        uint32_t ah[4];
        uint32_t al[4];
        ldm4(ah, &Qh[(warp * 16 + a_r) * QKS + a_k + ko]);
        ldm4(al, &Ql[(warp * 16 + a_r) * QKS + a_k + ko]);
#pragma unroll
        for (int jt = 0; jt < 4; jt++) {
            uint32_t th[4];
            uint32_t tl[4];
            ldm4(th, &Kh[(jt * 16 + b_r) * QKS + b_k + ko]);
            ldm4(tl, &Kl[(jt * 16 + b_r) * QKS + b_k + ko]);
            uint32_t bh0[2]; bh0[0] = th[0]; bh0[1] = th[1];
            uint32_t bh1[2]; bh1[0] = th[2]; bh1[1] = th[3];
            uint32_t bl0[2]; bl0[0] = tl[0]; bl0[1] = tl[1];
            uint32_t bl1[2]; bl1[0] = tl[2]; bl1[1] = tl[3];
            mma16816(accS[jt * 2],     ah, bh0);
            mma16816(accS[jt * 2],     ah, bl0);
            mma16816(accS[jt * 2],     al, bh0);
            mma16816(accS[jt * 2 + 1], ah, bh1);
            mma16816(accS[jt * 2 + 1], ah, bl1);
            mma16816(accS[jt * 2 + 1], al, bh1);
        }
    }

    // ---- scale + bias + mask, register softmax ----
    const float scale = 0.17677669529663687f;
    const int i0 = warp * 16 + gid;
    const int i1 = i0 + 8;
    const int i0d = i0 / 7;
    const int i0m = i0 % 7;
    const int i1d = i1 / 7;
    const int i1m = i1 % 7;
    const bool v0row = (i0 < 49);
    const bool v1row = (i1 < 49);

    float m0 = -1e30f;
    float m1 = -1e30f;
#pragma unroll
    for (int t = 0; t < 8; t++) {
        const int j0 = t * 8 + 2 * ctid;
        const int j1 = j0 + 1;
        const int jd0 = j0 / 7, jm0 = j0 % 7;
        const int jd1 = j1 / 7, jm1 = j1 % 7;
        float s00 = accS[t][0] * scale;
        float s01 = accS[t][1] * scale;
        float s10 = accS[t][2] * scale;
        float s11 = accS[t][3] * scale;
        if (v0row && j0 < 49) s00 += Bb[(i0d - jd0 + 6) * 13 + (i0m - jm0 + 6)];
        if (v0row && j1 < 49) s01 += Bb[(i0d - jd1 + 6) * 13 + (i0m - jm1 + 6)];
        if (v1row && j0 < 49) s10 += Bb[(i1d - jd0 + 6) * 13 + (i1m - jm0 + 6)];
        if (v1row && j1 < 49) s11 += Bb[(i1d - jd1 + 6) * 13 + (i1m - jm1 + 6)];
        if (j0 >= 49) { s00 = -1e30f; s10 = -1e30f; }
        if (j1 >= 49) { s01 = -1e30f; s11 = -1e30f; }
        accS[t][0] = s00;
        accS[t][1] = s01;
        accS[t][2] = s10;
        accS[t][3] = s11;
        m0 = fmaxf(m0, fmaxf(s00, s01));
        m1 = fmaxf(m1, fmaxf(s10, s11));
    }
    m0 = fmaxf(m0, __shfl_xor_sync(~0u, m0, 1));
    m0 = fmaxf(m0, __shfl_xor_sync(~0u, m0, 2));
    m1 = fmaxf(m1, __shfl_xor_sync(~0u, m1, 1));
    m1 = fmaxf(m1, __shfl_xor_sync(~0u, m1, 2));

    float sum0 = 0.f;
    float sum1 = 0.f;
#pragma unroll
    for (int t = 0; t < 8; t++) {
        float e00 = __expf(accS[t][0] - m0);
        float e01 = __expf(accS[t][1] - m0);
        float e10 = __expf(accS[t][2] - m1);
        float e11 = __expf(accS[t][3] - m1);
        accS[t][0] = e00;
        accS[t][1] = e01;
        accS[t][2] = e10;
        accS[t][3] = e11;
        sum0 += e00 + e01;
        sum1 += e10 + e11;
    }
    sum0 += __shfl_xor_sync(~0u, sum0, 1);
    sum0 += __shfl_xor_sync(~0u, sum0, 2);
    sum1 += __shfl_xor_sync(~0u, sum1, 1);
    sum1 += __shfl_xor_sync(~0u, sum1, 2);
    const float inv0 = 1.f / sum0;
    const float inv1 = 1.f / sum1;
#pragma unroll
    for (int t = 0; t < 8; t++) {
        accS[t][0] *= inv0;
        accS[t][1] *= inv0;
        accS[t][2] *= inv1;
        accS[t][3] *= inv1;
    }

    // ---- repack P into A-frags ----
    uint32_t pah[4][4];
    uint32_t pal[4][4];
#pragma unroll
    for (int s = 0; s < 4; s++) {
        const int te = 2 * s;
        const int to = 2 * s + 1;
        pah[s][0] = pack_hi2(accS[te][0], accS[te][1]);
        pal[s][0] = pack_lo2(accS[te][0], accS[te][1]);
        pah[s][1] = pack_hi2(accS[te][2], accS[te][3]);
        pal[s][1] = pack_lo2(accS[te][2], accS[te][3]);
        pah[s][2] = pack_hi2(accS[to][0], accS[to][1]);
        pal[s][2] = pack_lo2(accS[to][0], accS[to][1]);
        pah[s][3] = pack_hi2(accS[to][2], accS[to][3]);
        pal[s][3] = pack_lo2(accS[to][2], accS[to][3]);
    }

    // ---- O = P V ----
    float accO[4][4];
#pragma unroll
    for (int t = 0; t < 4; t++) {
#pragma unroll
        for (int e = 0; e < 4; e++) accO[t][e] = 0.f;
    }

#pragma unroll
    for (int s = 0; s < 4; s++) {
#pragma unroll
        for (int nb = 0; nb < 2; nb++) {
            uint32_t th[4];
            uint32_t tl[4];
            ldm4(th, &Vth[(nb * 16 + b_r) * VTS + b_k + s * 16]);
            ldm4(tl, &Vtl[(nb * 16 + b_r) * VTS + b_k + s * 16]);
            uint32_t bh0[2]; bh0[0] = th[0]; bh0[1] = th[1];
            uint32_t bh1[2]; bh1[0] = th[2]; bh1[1] = th[3];
            uint32_t bl0[2]; bl0[0] = tl[0]; bl0[1] = tl[1];
            uint32_t bl1[2]; bl1[0] = tl[2]; bl1[1] = tl[3];
            mma16816(accO[nb * 2],     pah[s], bh0);
            mma16816(accO[nb * 2],     pah[s], bl0);
            mma16816(accO[nb * 2],     pal[s], bh0);
            mma16816(accO[nb * 2 + 1], pah[s], bh1);
            mma16816(accO[nb * 2 + 1], pah[s], bl1);
            mma16816(accO[nb * 2 + 1], pal[s], bh1);
        }
    }

    // ---- store O ----
    if (v0row) {
        float* dst = g_attn + (w * P_ + i0) * C_ + h * HD_;
#pragma unroll
        for (int nt = 0; nt < 4; nt++) {
            float2 v;
            v.x = accO[nt][0];
            v.y = accO[nt][1];
            *(float2*)&dst[nt * 8 + 2 * ctid] = v;
        }
    }
    if (v1row) {
        float* dst = g_attn + (w * P_ + i1) * C_ + h * HD_;
#pragma unroll
        for (int nt = 0; nt < 4; nt++) {
            float2 v;
            v.x = accO[nt][2];
            v.y = accO[nt][3];
            *(float2*)&dst[nt * 8 + 2 * ctid] = v;
        }
    }
}

// ---------------------------------------------------------------------------
extern "C" void kernel_launch(void* const* d_in, const int* in_sizes, int n_in,
                              void* d_out, int out_size) {
    (void)in_sizes; (void)n_in; (void)out_size;
    const float* x      = (const float*)d_in[0];
    const float* w_qkv  = (const float*)d_in[1];
    const float* b_qkv  = (const float*)d_in[2];
    const float* relpos = (const float*)d_in[3];
    const float* w_out  = (const float*)d_in[4];
    const float* b_out  = (const float*)d_in[5];
    float* out = (float*)d_out;

    prep_weights<<<2304, 256>>>(w_qkv, w_out);

    dim3 g1(TOK_ / BM, QKVN_ / BN);
    qkv_mma<<<g1, 256>>>(x, b_qkv);

    attn_mma<<<BW_ * NH_, 128>>>(relpos);

    dim3 g3(TOK_ / BM, C_ / BN);
    proj_mma<<<g3, 256>>>(b_out, out);
}